// round 14
// baseline (speedup 1.0000x reference)
#include <cuda_runtime.h>
#include <cuda_fp16.h>
#include <cstdint>

#define MAXN 1000000
#define M 9
#define T 256

// Scratch (allocation-free rule: __device__ globals)
__device__ float4 d_pk[MAXN];   // {x, y, ut, ut1} fp32 — grad1 gather
__device__ float4 d_gc[MAXN];   // {x, y, half2(g0,g1), half2(g2,g3)} — grad2 single gather
__device__ float  d_acc;        // combined loss accumulator (memsetAsync-zeroed)

__device__ __forceinline__ float pack_h2(float a, float b) {
    __half2 h = __floats2half2_rn(a, b);
    return *reinterpret_cast<float*>(&h);
}
__device__ __forceinline__ float2 unpack_h2(float bits) {
    __half2 h = *reinterpret_cast<__half2*>(&bits);
    return __half22float2(h);
}

// Block-level reduce a float, ONE float atomicAdd per block (3907 total —
// per-warp atomics to a single address serialize catastrophically; R12).
__device__ __forceinline__ void block_reduce_add(float v, float* target) {
    __shared__ float warp_sums[32];
    int lane = threadIdx.x & 31;
    int wid  = threadIdx.x >> 5;
    #pragma unroll
    for (int off = 16; off > 0; off >>= 1)
        v += __shfl_down_sync(0xFFFFFFFFu, v, off);
    if (lane == 0) warp_sums[wid] = v;
    __syncthreads();
    int nwarps = (blockDim.x + 31) >> 5;
    if (wid == 0) {
        float s = (lane < nwarps) ? warp_sums[lane] : 0.0f;
        #pragma unroll
        for (int off = 16; off > 0; off >>= 1)
            s += __shfl_down_sync(0xFFFFFFFFu, s, off);
        if (lane == 0) atomicAdd(target, s);
    }
}

// K1: pure stream — build pack array only (no reduce tail: 7.9 vs 12.2 µs).
__global__ void k_pack(const float* __restrict__ ut,
                       const float* __restrict__ x,
                       const float* __restrict__ ut1,
                       int n) {
    int i = blockIdx.x * blockDim.x + threadIdx.x;
    if (i < n) {
        float2 xy = ((const float2*)x)[i];
        float4 pk;
        pk.x = xy.x;
        pk.y = xy.y;
        pk.z = ut[i];
        pk.w = ut1[i];
        d_pk[i] = pk;
    }
}

// K2: grad1 for ut and ut1 simultaneously — proven R9 form (fits 32 regs
// under (256,8); direct idx loads, no smem staging).
__global__ void __launch_bounds__(T, 8) k_grad1(const int* __restrict__ idx,
                        const float4* __restrict__ inv,
                        int n) {
    int k = blockIdx.x * blockDim.x + threadIdx.x;
    if (k >= n) return;
    float4 pk = d_pk[k];
    float sx = 0.f, sy = 0.f, s1x = 0.f, s1y = 0.f;
    #pragma unroll
    for (int m = 0; m < M; m++) {
        int nb = __ldg(&idx[k * M + m]);
        float4 q = __ldg(&d_pk[nb]);
        float dx = q.x - pk.x;
        float dy = q.y - pk.y;
        float du = q.z - pk.z;
        float du1 = q.w - pk.w;
        sx  += du  * dx;  sy  += du  * dy;
        s1x += du1 * dx;  s1y += du1 * dy;
    }
    float4 iv = __ldg(&inv[k]);
    float g0 = sx * iv.x + sy * iv.z;
    float g1 = sx * iv.y + sy * iv.w;
    float g2 = s1x * iv.x + s1y * iv.z;
    float g3 = s1x * iv.y + s1y * iv.w;

    float4 out;
    out.x = pk.x;
    out.y = pk.y;
    out.z = pack_h2(g0, g1);
    out.w = pack_h2(g2, g3);
    d_gc[k] = out;
}

// K3: grad2 + f + COMBINED loss (d^2 + 4*f^2) in one block reduce.
__global__ void __launch_bounds__(T, 8) k_grad2(const int* __restrict__ idx,
                        const float4* __restrict__ inv,
                        const float* __restrict__ ut,
                        const float* __restrict__ ut1,
                        const float* __restrict__ up,
                        const float* __restrict__ usol,
                        int n) {
    int k = blockIdx.x * blockDim.x + threadIdx.x;
    float contrib = 0.0f;
    if (k < n) {
        float4 gc = d_gc[k];
        float kx = gc.x, ky = gc.y;
        float2 gkA = unpack_h2(gc.z);
        float2 gkB = unpack_h2(gc.w);

        float s00 = 0.f, s01 = 0.f, s10 = 0.f, s11 = 0.f;
        float t00 = 0.f, t01 = 0.f, t10 = 0.f, t11 = 0.f;
        #pragma unroll
        for (int m = 0; m < M; m++) {
            int nb = __ldg(&idx[k * M + m]);
            float4 q = __ldg(&d_gc[nb]);
            float dx = q.x - kx;
            float dy = q.y - ky;
            float2 gA = unpack_h2(q.z);
            float2 gB = unpack_h2(q.w);
            float d0 = gA.x - gkA.x;
            float d1 = gA.y - gkA.y;
            float e0 = gB.x - gkB.x;
            float e1 = gB.y - gkB.y;
            s00 += d0 * dx; s01 += d0 * dy;
            s10 += d1 * dx; s11 += d1 * dy;
            t00 += e0 * dx; t01 += e0 * dy;
            t10 += e1 * dx; t11 += e1 * dy;
        }
        float4 iv = __ldg(&inv[k]);
        float u_xx  = s00 * iv.x + s01 * iv.z;
        float u_yy  = s10 * iv.y + s11 * iv.w;
        float u_xx1 = t00 * iv.x + t01 * iv.z;
        float u_yy1 = t10 * iv.y + t11 * iv.w;

        float utk  = __ldg(&ut[k]);
        float ut1k = __ldg(&ut1[k]);
        float f = ut1k - utk
                - 0.01f * ((0.01f * (u_xx + u_yy) + utk - utk * utk * utk)
                         + (0.01f * (u_xx1 + u_yy1) + ut1k - ut1k * ut1k * ut1k));
        float d = __ldg(&up[k]) - __ldg(&usol[k]);
        contrib = d * d + 4.0f * (f * f);
    }
    block_reduce_add(contrib, &d_acc);
}

extern "C" void kernel_launch(void* const* d_in, const int* in_sizes, int n_in,
                              void* d_out, int out_size) {
    const float* up   = (const float*)d_in[0];
    const float* usol = (const float*)d_in[1];
    const float* ut   = (const float*)d_in[2];
    const float* x    = (const float*)d_in[3];
    const float* ut1  = (const float*)d_in[4];
    const int*   idx  = (const int*)d_in[5];
    const float4* inv = (const float4*)d_in[6];
    int n = in_sizes[0];

    // Zero the accumulator without a kernel launch (graph-capturable memset).
    void* acc_ptr = nullptr;
    cudaGetSymbolAddress(&acc_ptr, d_acc);
    cudaMemsetAsync(acc_ptr, 0, sizeof(float));

    int B = (n + T - 1) / T;

    k_pack<<<B, T>>>(ut, x, ut1, n);
    k_grad1<<<B, T>>>(idx, inv, n);
    k_grad2<<<B, T>>>(idx, inv, ut, ut1, up, usol, n);

    // Final scalar: D2D copy instead of a 1-thread kernel (saves ~4 µs).
    cudaMemcpyAsync(d_out, acc_ptr, sizeof(float), cudaMemcpyDeviceToDevice);
}

// round 15
// speedup vs baseline: 1.0283x; 1.0283x over previous
#include <cuda_runtime.h>
#include <cuda_fp16.h>
#include <cstdint>

#define MAXN 1000000
#define M 9
#define T 256
#define NW (T / 32)          // warps per block

// Scratch (allocation-free rule: __device__ globals)
__device__ float4 d_pk[MAXN];   // {x, y, ut, ut1} fp32 — grad1 gather
__device__ float4 d_gc[MAXN];   // {x, y, half2(g0,g1), half2(g2,g3)} — grad2 single gather

__device__ __forceinline__ float pack_h2(float a, float b) {
    __half2 h = __floats2half2_rn(a, b);
    return *reinterpret_cast<float*>(&h);
}
__device__ __forceinline__ float2 unpack_h2(float bits) {
    __half2 h = *reinterpret_cast<__half2*>(&bits);
    return __half22float2(h);
}

// Block-level reduce a float, ONE float atomicAdd per block (3907 total).
__device__ __forceinline__ void block_reduce_add(float v, float* target) {
    __shared__ float warp_sums[32];
    int lane = threadIdx.x & 31;
    int wid  = threadIdx.x >> 5;
    #pragma unroll
    for (int off = 16; off > 0; off >>= 1)
        v += __shfl_down_sync(0xFFFFFFFFu, v, off);
    if (lane == 0) warp_sums[wid] = v;
    __syncthreads();
    int nwarps = (blockDim.x + 31) >> 5;
    if (wid == 0) {
        float s = (lane < nwarps) ? warp_sums[lane] : 0.0f;
        #pragma unroll
        for (int off = 16; off > 0; off >>= 1)
            s += __shfl_down_sync(0xFFFFFFFFu, s, off);
        if (lane == 0) atomicAdd(target, s);
    }
}

// Warp-private idx staging: 9 coalesced LDG (9 wf vs 81 for stride-36 direct)
// + 9 STS + __syncwarp + stride-9 LDS (conflict-free, gcd(9,32)=1).
// No block barrier — warps stay decoupled (R7's __syncthreads coupling avoided).
__device__ __forceinline__ void warp_stage_idx(const int* __restrict__ idx,
                                               int* sw, int warp_k0, int n,
                                               int lane, int nb[M]) {
    int wbase = warp_k0 * M;             // first idx element for this warp
    int nint = n * M;
    #pragma unroll
    for (int j = 0; j < M; j++) {
        int gi = wbase + j * 32 + lane;
        sw[j * 32 + lane] = (gi < nint) ? __ldg(&idx[gi]) : 0;
    }
    __syncwarp();
    #pragma unroll
    for (int m = 0; m < M; m++) nb[m] = sw[lane * M + m];
}

// K1: pure stream — build pack array only.
__global__ void k_pack(const float* __restrict__ ut,
                       const float* __restrict__ x,
                       const float* __restrict__ ut1,
                       int n) {
    int i = blockIdx.x * blockDim.x + threadIdx.x;
    if (i < n) {
        float2 xy = ((const float2*)x)[i];
        float4 pk;
        pk.x = xy.x;
        pk.y = xy.y;
        pk.z = ut[i];
        pk.w = ut1[i];
        d_pk[i] = pk;
    }
}

// K2: grad1 for ut and ut1 simultaneously.
__global__ void __launch_bounds__(T, 8) k_grad1(const int* __restrict__ idx,
                        const float4* __restrict__ inv,
                        int n) {
    __shared__ int s_idx[T * M];
    int lane = threadIdx.x & 31;
    int wid  = threadIdx.x >> 5;
    int warp_k0 = blockIdx.x * T + wid * 32;

    int nb[M];
    warp_stage_idx(idx, s_idx + wid * (32 * M), warp_k0, n, lane, nb);

    int k = warp_k0 + lane;
    if (k >= n) return;

    float4 pk = d_pk[k];
    float sx = 0.f, sy = 0.f, s1x = 0.f, s1y = 0.f;
    #pragma unroll
    for (int m = 0; m < M; m++) {
        float4 q = __ldg(&d_pk[nb[m]]);
        float dx = q.x - pk.x;
        float dy = q.y - pk.y;
        float du = q.z - pk.z;
        float du1 = q.w - pk.w;
        sx  += du  * dx;  sy  += du  * dy;
        s1x += du1 * dx;  s1y += du1 * dy;
    }
    float4 iv = __ldg(&inv[k]);
    float g0 = sx * iv.x + sy * iv.z;
    float g1 = sx * iv.y + sy * iv.w;
    float g2 = s1x * iv.x + s1y * iv.z;
    float g3 = s1x * iv.y + s1y * iv.w;

    float4 out;
    out.x = pk.x;
    out.y = pk.y;
    out.z = pack_h2(g0, g1);
    out.w = pack_h2(g2, g3);
    d_gc[k] = out;
}

// K3: grad2 + f + COMBINED loss (d^2 + 4*f^2); per-block atomic straight
// into d_out (pre-zeroed by memsetAsync) — no finalize node at all.
__global__ void __launch_bounds__(T, 8) k_grad2(const int* __restrict__ idx,
                        const float4* __restrict__ inv,
                        const float* __restrict__ ut,
                        const float* __restrict__ ut1,
                        const float* __restrict__ up,
                        const float* __restrict__ usol,
                        int n, float* __restrict__ out) {
    __shared__ int s_idx[T * M];
    int lane = threadIdx.x & 31;
    int wid  = threadIdx.x >> 5;
    int warp_k0 = blockIdx.x * T + wid * 32;

    int nb[M];
    warp_stage_idx(idx, s_idx + wid * (32 * M), warp_k0, n, lane, nb);

    int k = warp_k0 + lane;
    float contrib = 0.0f;
    if (k < n) {
        float4 gc = d_gc[k];
        float kx = gc.x, ky = gc.y;
        float2 gkA = unpack_h2(gc.z);
        float2 gkB = unpack_h2(gc.w);

        float s00 = 0.f, s01 = 0.f, s10 = 0.f, s11 = 0.f;
        float t00 = 0.f, t01 = 0.f, t10 = 0.f, t11 = 0.f;
        #pragma unroll
        for (int m = 0; m < M; m++) {
            float4 q = __ldg(&d_gc[nb[m]]);
            float dx = q.x - kx;
            float dy = q.y - ky;
            float2 gA = unpack_h2(q.z);
            float2 gB = unpack_h2(q.w);
            float d0 = gA.x - gkA.x;
            float d1 = gA.y - gkA.y;
            float e0 = gB.x - gkB.x;
            float e1 = gB.y - gkB.y;
            s00 += d0 * dx; s01 += d0 * dy;
            s10 += d1 * dx; s11 += d1 * dy;
            t00 += e0 * dx; t01 += e0 * dy;
            t10 += e1 * dx; t11 += e1 * dy;
        }
        float4 iv = __ldg(&inv[k]);
        float u_xx  = s00 * iv.x + s01 * iv.z;
        float u_yy  = s10 * iv.y + s11 * iv.w;
        float u_xx1 = t00 * iv.x + t01 * iv.z;
        float u_yy1 = t10 * iv.y + t11 * iv.w;

        float utk  = __ldg(&ut[k]);
        float ut1k = __ldg(&ut1[k]);
        float f = ut1k - utk
                - 0.01f * ((0.01f * (u_xx + u_yy) + utk - utk * utk * utk)
                         + (0.01f * (u_xx1 + u_yy1) + ut1k - ut1k * ut1k * ut1k));
        float d = __ldg(&up[k]) - __ldg(&usol[k]);
        contrib = d * d + 4.0f * (f * f);
    }
    block_reduce_add(contrib, out);
}

extern "C" void kernel_launch(void* const* d_in, const int* in_sizes, int n_in,
                              void* d_out, int out_size) {
    const float* up   = (const float*)d_in[0];
    const float* usol = (const float*)d_in[1];
    const float* ut   = (const float*)d_in[2];
    const float* x    = (const float*)d_in[3];
    const float* ut1  = (const float*)d_in[4];
    const int*   idx  = (const int*)d_in[5];
    const float4* inv = (const float4*)d_in[6];
    int n = in_sizes[0];

    // Accumulate directly into d_out: zero it first (it arrives poisoned).
    cudaMemsetAsync(d_out, 0, sizeof(float));

    int B = (n + T - 1) / T;

    k_pack<<<B, T>>>(ut, x, ut1, n);
    k_grad1<<<B, T>>>(idx, inv, n);
    k_grad2<<<B, T>>>(idx, inv, ut, ut1, up, usol, n, (float*)d_out);
}